// round 9
// baseline (speedup 1.0000x reference)
#include <cuda_runtime.h>
#include <math.h>

// ---------------- problem constants ----------------
#define BATCH   128
#define IN_DIM  128
#define HID     512
#define STK     64
#define GD      2048            // 4*HID gate rows
#define KIN     (IN_DIM + STK)  // 192 = Wih cols
#define KTOT    (KIN + HID)     // 704 combined K
#define MAXT    259
#define NSTEPS  259
#define PH1_LAST 128            // t<=128 uses x[t]; t>=129 x==0
#define OUT_T0  129             // first output step
#define RDIM    194             // STK + IN_DIM + 2

// ---------------- persistent device state ----------------
__device__ float g_Wg[GD * KTOT];       // gate-interleaved [Wih|Whh], row n=4*j+gate
__device__ float g_bias[GD];            // bih+bhh, interleaved same way
__device__ float g_WrT[HID * RDIM];     // Wr transposed: [k][r]
__device__ float g_h[2][BATCH * HID];   // ping-pong hidden
__device__ float g_c[BATCH * HID];
__device__ float g_rt[BATCH * STK];
__device__ float g_s[BATCH * MAXT];
__device__ float g_V[BATCH * MAXT * STK];

// ---------------- prep: rearrange weights + zero state ----------------
__global__ void k_prep(const float* __restrict__ Wih, const float* __restrict__ bih,
                       const float* __restrict__ Whh, const float* __restrict__ bhh,
                       const float* __restrict__ Wr)
{
    int idx = blockIdx.x * blockDim.x + threadIdx.x;
    int nthreads = gridDim.x * blockDim.x;

    // combined, gate-interleaved weight matrix: row n = 4*j + gate
    for (int i = idx; i < GD * KTOT; i += nthreads) {
        int n = i / KTOT, k = i - n * KTOT;
        int j = n >> 2, gate = n & 3;
        int src = gate * HID + j;
        float v = (k < KIN) ? Wih[src * KIN + k] : Whh[src * HID + (k - KIN)];
        g_Wg[i] = v;
    }
    for (int n = idx; n < GD; n += nthreads) {
        int j = n >> 2, gate = n & 3;
        int src = gate * HID + j;
        g_bias[n] = bih[src] + bhh[src];
    }
    // transposed readout weights for coalesced access
    for (int i = idx; i < HID * RDIM; i += nthreads) {
        int k = i / RDIM, r = i - k * RDIM;
        g_WrT[i] = Wr[r * HID + k];
    }
    // zero recurrent state (V never reads unwritten slots, skip it)
    for (int i = idx; i < BATCH * HID; i += nthreads) { g_h[0][i] = 0.f; g_c[i] = 0.f; }
    for (int i = idx; i < BATCH * STK; i += nthreads) g_rt[i] = 0.f;
    for (int i = idx; i < BATCH * MAXT; i += nthreads) g_s[i] = 0.f;
}

// ---------------- K1: gates GEMM + LSTM cell (fused) ----------------
// g(128 x 2048) = [x_t | rt | h_prev](128 x 704) @ Wg^T, then cell update.
// Tiles: BM=32 (batch), BN=64 (gate rows = 16 units x 4 gates), BK=32.
// 128 threads, 4x4 micro-tile each; thread's 4 columns == the 4 gates of one unit.
#define BM 32
#define BN 64
#define BKK 32

__global__ void __launch_bounds__(128, 1)
k_gates(const float* __restrict__ x, int t)
{
    const int cur = t & 1;
    const float* __restrict__ hprev = g_h[cur];
    float* __restrict__ hnew = g_h[cur ^ 1];

    __shared__ __align__(16) float As[BKK][BM + 4];  // [k][b], row 36 floats (144B, 16B-mult)
    __shared__ __align__(16) float Bs[BKK][BN + 4];  // [k][n], row 68 floats (272B, 16B-mult)

    const int tid = threadIdx.x;
    const int tx = tid & 15;   // 0..15 -> 4-col group (one hidden unit's 4 gates)
    const int ty = tid >> 4;   // 0..7  -> 4-row group
    const int bn0 = blockIdx.x * BN;
    const int bm0 = blockIdx.y * BM;

    float acc[4][4];
#pragma unroll
    for (int i = 0; i < 4; i++)
#pragma unroll
        for (int j = 0; j < 4; j++) acc[i][j] = 0.f;

    const bool haveX = (t <= PH1_LAST);
    const int kStart = haveX ? 0 : IN_DIM;   // phase 2: x is exactly zero

    for (int k0 = kStart; k0 < KTOT; k0 += BKK) {
        // load A tile (xin_full = [x_t | rt | h_prev]) : 1024 elems, 8/thread
#pragma unroll
        for (int i = 0; i < 8; i++) {
            int idx = tid + i * 128;
            int k = idx & 31;
            int b = idx >> 5;
            int gk = k0 + k;
            int gb = bm0 + b;
            float v;
            if (gk < IN_DIM)      v = haveX ? x[(t * BATCH + gb) * IN_DIM + gk] : 0.f;
            else if (gk < KIN)    v = g_rt[gb * STK + (gk - IN_DIM)];
            else                  v = hprev[gb * HID + (gk - KIN)];
            As[k][b] = v;
        }
        // load B tile: 2048 elems, 16/thread, coalesced over k
#pragma unroll
        for (int i = 0; i < 16; i++) {
            int idx = tid + i * 128;
            int k = idx & 31;
            int n = idx >> 5;
            Bs[k][n] = g_Wg[(bn0 + n) * KTOT + k0 + k];
        }
        __syncthreads();

#pragma unroll
        for (int kk = 0; kk < BKK; kk++) {
            float4 a  = *(const float4*)&As[kk][ty * 4];
            float4 bq = *(const float4*)&Bs[kk][tx * 4];
            float av[4] = {a.x, a.y, a.z, a.w};
            float bv[4] = {bq.x, bq.y, bq.z, bq.w};
#pragma unroll
            for (int i = 0; i < 4; i++)
#pragma unroll
                for (int j = 0; j < 4; j++)
                    acc[i][j] += av[i] * bv[j];
        }
        __syncthreads();
    }

    // epilogue: 4 cols of this thread = gates (i,f,g,o) of unit jj
    const int n0 = bn0 + tx * 4;
    const int jj = n0 >> 2;
    const float bi_ = g_bias[n0 + 0];
    const float bf_ = g_bias[n0 + 1];
    const float bg_ = g_bias[n0 + 2];
    const float bo_ = g_bias[n0 + 3];
#pragma unroll
    for (int i = 0; i < 4; i++) {
        int b = bm0 + ty * 4 + i;
        float gi = acc[i][0] + bi_;
        float gf = acc[i][1] + bf_;
        float gg = acc[i][2] + bg_;
        float go = acc[i][3] + bo_;
        float si = 1.f / (1.f + expf(-gi));
        float sf = 1.f / (1.f + expf(-gf));
        float so = 1.f / (1.f + expf(-go));
        float tg = tanhf(gg);
        float cold = g_c[b * HID + jj];
        float cnew = sf * cold + si * tg;
        g_c[b * HID + jj] = cnew;
        hnew[b * HID + jj] = so * tanhf(cnew);
    }
}

// ---------------- K2: readout GEMM + stack update + (phase2) log-softmax ----
// 32 blocks x 256 threads; each block owns 4 batches (shares the Wr stream).
__global__ void __launch_bounds__(256, 1)
k_readout_stack(const float* __restrict__ br, float* __restrict__ out, int t)
{
    const int cur = t & 1;
    const float* __restrict__ h = g_h[cur ^ 1];  // h_new from K1

    __shared__ float hsh[4][HID];
    __shared__ float osh[4][RDIM];
    __shared__ float utdt[4][2];
    __shared__ float ssuf[272];
    __shared__ float sorig[272];
    __shared__ float aA[272];
    __shared__ float ctot[16];
    __shared__ float part[4][STK];

    const int tid = threadIdx.x;
    const int b0 = blockIdx.x * 4;
    const int lane = tid & 31;
    const int warp = tid >> 5;

    // load 4 h rows
#pragma unroll
    for (int i = 0; i < 8; i++) {
        int idx = tid + i * 256;
        hsh[idx >> 9][idx & 511] = h[(b0 + (idx >> 9)) * HID + (idx & 511)];
    }
    __syncthreads();

    // readout: out[b][r] = h[b] . Wr[r] + br[r]   (thread r, 4 batches per thread)
    if (tid < RDIM) {
        const int r = tid;
        float a0 = br[r], a1 = a0, a2 = a0, a3 = a0;
#pragma unroll 8
        for (int k = 0; k < HID; k++) {
            float w = g_WrT[k * RDIM + r];
            a0 += hsh[0][k] * w;
            a1 += hsh[1][k] * w;
            a2 += hsh[2][k] * w;
            a3 += hsh[3][k] * w;
        }
        osh[0][r] = a0; osh[1][r] = a1; osh[2][r] = a2; osh[3][r] = a3;
        if (r < STK) {   // V[:, t, :] was zero -> set
            g_V[((size_t)(b0 + 0) * MAXT + t) * STK + r] = a0;
            g_V[((size_t)(b0 + 1) * MAXT + t) * STK + r] = a1;
            g_V[((size_t)(b0 + 2) * MAXT + t) * STK + r] = a2;
            g_V[((size_t)(b0 + 3) * MAXT + t) * STK + r] = a3;
        }
    }
    __syncthreads();
    if (tid < 4) {
        utdt[tid][0] = 1.f / (1.f + expf(-osh[tid][RDIM - 2]));  // ut
        utdt[tid][1] = 1.f / (1.f + expf(-osh[tid][RDIM - 1]));  // dt
    }
    __syncthreads();

    const int n = t + 1;            // active stack slots: tau = 0..t
    const int nc = (n + 31) >> 5;   // <= 9 chunks of 32

    for (int bi = 0; bi < 4; bi++) {
        const int b = b0 + bi;
        // Phase A: per-warp inclusive suffix scan over 32-chunks of old s
        for (int c = warp; c * 32 < n; c += 8) {
            int tau = c * 32 + lane;
            float v = (tau < n) ? g_s[b * MAXT + tau] : 0.f;
            if (tau < n) sorig[tau] = v;
#pragma unroll
            for (int d = 1; d < 32; d <<= 1) {
                float o = __shfl_down_sync(0xffffffffu, v, d);
                if (lane + d < 32) v += o;
            }
            if (tau < n) ssuf[tau] = v;
            if (lane == 0) ctot[c] = v;
        }
        __syncthreads();
        // Phase B: exclusive suffix of chunk totals
        if (tid == 0) {
            float run = 0.f;
            for (int c = nc - 1; c >= 0; c--) {
                float tc = ctot[c];
                ctot[c] = run;
                run += tc;
            }
        }
        __syncthreads();
        // Phase C: prod -> sp -> A, write new s
        {
            float ut = utdt[bi][0], dt = utdt[bi][1];
            for (int tau = tid; tau < n; tau += 256) {
                float so_ = sorig[tau];
                float prod = (ssuf[tau] + ctot[tau >> 5]) - so_;  // excl. suffix sum
                float sp = fmaxf(0.f, so_ - fmaxf(0.f, ut - prod));
                if (tau == t) sp = dt;
                float inner = fmaxf(0.f, 1.f - prod - sp);
                aA[tau] = fminf(sp, inner);
                g_s[b * MAXT + tau] = sp;
            }
        }
        __syncthreads();
        // Phase D: rt[d] = sum_tau A[tau] * V[b][tau][d]
        {
            int d = tid & 63;
            int grp = tid >> 6;
            float racc = 0.f;
            for (int tau = grp; tau < n; tau += 4)
                racc += aA[tau] * g_V[((size_t)b * MAXT + tau) * STK + d];
            part[grp][d] = racc;
        }
        __syncthreads();
        if (tid < STK)
            g_rt[b * STK + tid] = part[0][tid] + part[1][tid] + part[2][tid] + part[3][tid];
        __syncthreads();
    }

    // Phase E: log-softmax of ot (out[:,64:192]) for output steps
    if (t >= OUT_T0) {
        const int bi = tid >> 6;
        const int q = tid & 63;
        float v0 = osh[bi][STK + 2 * q];
        float v1 = osh[bi][STK + 2 * q + 1];
        part[bi][q] = fmaxf(v0, v1);
        __syncthreads();
#pragma unroll
        for (int sft = 32; sft >= 1; sft >>= 1) {
            if (q < sft) part[bi][q] = fmaxf(part[bi][q], part[bi][q + sft]);
            __syncthreads();
        }
        float m = part[bi][0];
        __syncthreads();
        part[bi][q] = expf(v0 - m) + expf(v1 - m);
        __syncthreads();
#pragma unroll
        for (int sft = 32; sft >= 1; sft >>= 1) {
            if (q < sft) part[bi][q] += part[bi][q + sft];
            __syncthreads();
        }
        float lse = m + logf(part[bi][0]);
        int b = b0 + bi;
        size_t base = ((size_t)(t - OUT_T0) * BATCH + b) * IN_DIM;
        out[base + 2 * q]     = v0 - lse;
        out[base + 2 * q + 1] = v1 - lse;
    }
}

// ---------------- launch ----------------
extern "C" void kernel_launch(void* const* d_in, const int* in_sizes, int n_in,
                              void* d_out, int out_size)
{
    (void)in_sizes; (void)n_in; (void)out_size;
    const float* x   = (const float*)d_in[0];
    const float* Wih = (const float*)d_in[1];
    const float* bih = (const float*)d_in[2];
    const float* Whh = (const float*)d_in[3];
    const float* bhh = (const float*)d_in[4];
    const float* Wr  = (const float*)d_in[5];
    const float* br  = (const float*)d_in[6];
    float* out = (float*)d_out;

    k_prep<<<512, 256>>>(Wih, bih, Whh, bhh, Wr);

    for (int t = 0; t < NSTEPS; t++) {
        k_gates<<<dim3(GD / BN, BATCH / BM), 128>>>(x, t);
        k_readout_stack<<<BATCH / 4, 256>>>(br, out, t);
    }
}

// round 10
// speedup vs baseline: 1.8547x; 1.8547x over previous
#include <cuda_runtime.h>
#include <math.h>

// ---------------- problem constants ----------------
#define BATCH   128
#define IN_DIM  128
#define HID     512
#define STK     64
#define GD      2048            // 4*HID gate rows
#define KIN     (IN_DIM + STK)  // 192 = Wih cols
#define KTOT    (KIN + HID)     // 704 combined K
#define MAXT    259
#define NSTEPS  259
#define PH1_LAST 128            // t<=128 uses x[t]; t>=129 x==0
#define OUT_T0  129             // first output step
#define RDIM    194             // STK + IN_DIM + 2

// ---------------- persistent device state ----------------
__device__ float g_Wg[GD * KTOT];       // gate-interleaved [Wih|Whh], row n=4*j+gate
__device__ float g_bias[GD];            // bih+bhh, interleaved same way
__device__ float g_WrT[HID * RDIM];     // Wr transposed: [k][r]
__device__ float g_h[2][BATCH * HID];   // ping-pong hidden
__device__ float g_c[BATCH * HID];
__device__ float g_rt[BATCH * STK];
__device__ float g_s[BATCH * MAXT];
__device__ float g_V[BATCH * MAXT * STK];

// ---------------- prep: rearrange weights + zero state ----------------
__global__ void k_prep(const float* __restrict__ Wih, const float* __restrict__ bih,
                       const float* __restrict__ Whh, const float* __restrict__ bhh,
                       const float* __restrict__ Wr)
{
    int idx = blockIdx.x * blockDim.x + threadIdx.x;
    int nthreads = gridDim.x * blockDim.x;

    // combined, gate-interleaved weight matrix: row n = 4*j + gate
    for (int i = idx; i < GD * KTOT; i += nthreads) {
        int n = i / KTOT, k = i - n * KTOT;
        int j = n >> 2, gate = n & 3;
        int src = gate * HID + j;
        float v = (k < KIN) ? Wih[src * KIN + k] : Whh[src * HID + (k - KIN)];
        g_Wg[i] = v;
    }
    for (int n = idx; n < GD; n += nthreads) {
        int j = n >> 2, gate = n & 3;
        int src = gate * HID + j;
        g_bias[n] = bih[src] + bhh[src];
    }
    // transposed readout weights for coalesced access
    for (int i = idx; i < HID * RDIM; i += nthreads) {
        int k = i / RDIM, r = i - k * RDIM;
        g_WrT[i] = Wr[r * HID + k];
    }
    // zero recurrent state (V never reads unwritten slots, skip it)
    for (int i = idx; i < BATCH * HID; i += nthreads) { g_h[0][i] = 0.f; g_c[i] = 0.f; }
    for (int i = idx; i < BATCH * STK; i += nthreads) g_rt[i] = 0.f;
    for (int i = idx; i < BATCH * MAXT; i += nthreads) g_s[i] = 0.f;
}

// ---------------- K1: gates GEMM + LSTM cell (fused) ----------------
// g(128 x 2048) = [x_t | rt | h_prev](128 x 704) @ Wg^T, then cell update.
// 256 threads, BM=32 (batch) x BN=64 (gates), BK=32.
// Thread = 2 batch rows x 4 gate cols; the 4 cols == the i/f/g/o of one unit.
// Double-buffered smem: global loads staged in registers overlap compute.
#define BM 32
#define BN 64
#define BKK 32

__global__ void __launch_bounds__(256, 1)
k_gates(const float* __restrict__ x, int t)
{
    const int cur = t & 1;
    const float* __restrict__ hprev = g_h[cur];
    float* __restrict__ hnew = g_h[cur ^ 1];

    __shared__ __align__(16) float As[2][BKK][BM + 2];  // [k][b], 34-float rows
    __shared__ __align__(16) float Bs[2][BKK][BN + 4];  // [k][n], 68-float rows

    const int tid = threadIdx.x;
    const int tx = tid & 15;    // 0..15 -> 4-col group (one hidden unit)
    const int ty = tid >> 4;    // 0..15 -> 2-row group
    const int bn0 = blockIdx.x * BN;
    const int bm0 = blockIdx.y * BM;

    const bool haveX = (t <= PH1_LAST);
    const int kStart = haveX ? 0 : IN_DIM;   // phase 2: x is exactly zero
    const int nt = (KTOT - kStart) / BKK;
    const float* __restrict__ xrow = x + (size_t)t * BATCH * IN_DIM;

    float acc[2][4];
#pragma unroll
    for (int i = 0; i < 2; i++)
#pragma unroll
        for (int j = 0; j < 4; j++) acc[i][j] = 0.f;

    // ---- prologue: load tile 0 (each K-tile has a single uniform A-source) ----
    {
        const int k0 = kStart;
        const float* srcA; int strideA, offA;
        if (k0 < IN_DIM)      { srcA = xrow;  strideA = IN_DIM; offA = k0; }
        else if (k0 < KIN)    { srcA = g_rt;  strideA = STK;    offA = k0 - IN_DIM; }
        else                  { srcA = hprev; strideA = HID;    offA = k0 - KIN; }
#pragma unroll
        for (int i = 0; i < 4; i++) {
            int idx = tid + i * 256; int k = idx & 31, b = idx >> 5;
            As[0][k][b] = srcA[(bm0 + b) * strideA + offA + k];
        }
#pragma unroll
        for (int i = 0; i < 8; i++) {
            int idx = tid + i * 256; int k = idx & 31, n = idx >> 5;
            Bs[0][k][n] = g_Wg[(size_t)(bn0 + n) * KTOT + k0 + k];
        }
    }
    __syncthreads();

    for (int it = 0; it < nt; ++it) {
        const int p = it & 1;
        float rA[4], rB[8];
        const bool more = (it + 1 < nt);
        if (more) {
            const int k0 = kStart + (it + 1) * BKK;
            const float* srcA; int strideA, offA;
            if (k0 < IN_DIM)      { srcA = xrow;  strideA = IN_DIM; offA = k0; }
            else if (k0 < KIN)    { srcA = g_rt;  strideA = STK;    offA = k0 - IN_DIM; }
            else                  { srcA = hprev; strideA = HID;    offA = k0 - KIN; }
#pragma unroll
            for (int i = 0; i < 4; i++) {
                int idx = tid + i * 256; int k = idx & 31, b = idx >> 5;
                rA[i] = srcA[(bm0 + b) * strideA + offA + k];
            }
#pragma unroll
            for (int i = 0; i < 8; i++) {
                int idx = tid + i * 256; int k = idx & 31, n = idx >> 5;
                rB[i] = g_Wg[(size_t)(bn0 + n) * KTOT + k0 + k];
            }
        }

#pragma unroll
        for (int kk = 0; kk < BKK; kk++) {
            float2 a  = *(const float2*)&As[p][kk][ty * 2];
            float4 bq = *(const float4*)&Bs[p][kk][tx * 4];
            acc[0][0] = fmaf(a.x, bq.x, acc[0][0]);
            acc[0][1] = fmaf(a.x, bq.y, acc[0][1]);
            acc[0][2] = fmaf(a.x, bq.z, acc[0][2]);
            acc[0][3] = fmaf(a.x, bq.w, acc[0][3]);
            acc[1][0] = fmaf(a.y, bq.x, acc[1][0]);
            acc[1][1] = fmaf(a.y, bq.y, acc[1][1]);
            acc[1][2] = fmaf(a.y, bq.z, acc[1][2]);
            acc[1][3] = fmaf(a.y, bq.w, acc[1][3]);
        }

        if (more) {
            const int q = p ^ 1;
#pragma unroll
            for (int i = 0; i < 4; i++) {
                int idx = tid + i * 256; As[q][idx & 31][idx >> 5] = rA[i];
            }
#pragma unroll
            for (int i = 0; i < 8; i++) {
                int idx = tid + i * 256; Bs[q][idx & 31][idx >> 5] = rB[i];
            }
        }
        __syncthreads();
    }

    // epilogue: 4 cols of this thread = gates (i,f,g,o) of unit jj
    const int n0 = bn0 + tx * 4;
    const int jj = n0 >> 2;
    const float bi_ = g_bias[n0 + 0];
    const float bf_ = g_bias[n0 + 1];
    const float bg_ = g_bias[n0 + 2];
    const float bo_ = g_bias[n0 + 3];
#pragma unroll
    for (int i = 0; i < 2; i++) {
        int b = bm0 + ty * 2 + i;
        float gi = acc[i][0] + bi_;
        float gf = acc[i][1] + bf_;
        float gg = acc[i][2] + bg_;
        float go = acc[i][3] + bo_;
        float si = 1.f / (1.f + expf(-gi));
        float sf = 1.f / (1.f + expf(-gf));
        float so = 1.f / (1.f + expf(-go));
        float tg = tanhf(gg);
        float cold = g_c[b * HID + jj];
        float cnew = sf * cold + si * tg;
        g_c[b * HID + jj] = cnew;
        hnew[b * HID + jj] = so * tanhf(cnew);
    }
}

// ---------------- K2: readout GEMM + stack update + (phase2) log-softmax ----
// 64 blocks x 256 threads; each block owns 2 batches (w reused for 2 FMA/load).
__global__ void __launch_bounds__(256, 1)
k_readout_stack(const float* __restrict__ br, float* __restrict__ out, int t)
{
    const float* __restrict__ h = g_h[(t & 1) ^ 1];  // h_new from K1

    __shared__ float hsh[2][HID];
    __shared__ float osh[2][RDIM];
    __shared__ float s_ut[2], s_dt[2];
    __shared__ float ssuf[272];
    __shared__ float sorig[272];
    __shared__ float aA[272];
    __shared__ float ctot[16];
    __shared__ float part[4][STK];
    __shared__ float redm[8], redv[2], redl[2];

    const int tid = threadIdx.x;
    const int lane = tid & 31;
    const int warp = tid >> 5;
    const int b0 = blockIdx.x * 2;

    // load 2 h rows (1024 floats)
#pragma unroll
    for (int i = 0; i < 4; i++) {
        int idx = tid + i * 256;
        hsh[idx >> 9][idx & 511] = h[(b0 + (idx >> 9)) * HID + (idx & 511)];
    }
    __syncthreads();

    // readout: out[b][r] = h[b] . Wr[r] + br[r]
    if (tid < RDIM) {
        const int r = tid;
        float a0 = br[r], a1 = a0;
#pragma unroll 8
        for (int k = 0; k < HID; k++) {
            float w = g_WrT[k * RDIM + r];
            a0 = fmaf(hsh[0][k], w, a0);
            a1 = fmaf(hsh[1][k], w, a1);
        }
        osh[0][r] = a0; osh[1][r] = a1;
        if (r < STK) {   // V[:, t, :] was zero -> set
            g_V[((size_t)(b0 + 0) * MAXT + t) * STK + r] = a0;
            g_V[((size_t)(b0 + 1) * MAXT + t) * STK + r] = a1;
        }
    }
    __syncthreads();
    if (tid < 2) {
        s_ut[tid] = 1.f / (1.f + expf(-osh[tid][RDIM - 2]));
        s_dt[tid] = 1.f / (1.f + expf(-osh[tid][RDIM - 1]));
    }
    __syncthreads();

    const int n = t + 1;            // active stack slots: tau = 0..t
    const int nc = (n + 31) >> 5;   // <= 9 chunks of 32

    for (int bi = 0; bi < 2; bi++) {
        const int b = b0 + bi;
        // Phase A: per-warp inclusive suffix scan over 32-chunks of old s
        for (int c = warp; c * 32 < n; c += 8) {
            int tau = c * 32 + lane;
            float v = (tau < n) ? g_s[b * MAXT + tau] : 0.f;
            if (tau < n) sorig[tau] = v;
#pragma unroll
            for (int d = 1; d < 32; d <<= 1) {
                float o = __shfl_down_sync(0xffffffffu, v, d);
                if (lane + d < 32) v += o;
            }
            if (tau < n) ssuf[tau] = v;
            if (lane == 0) ctot[c] = v;
        }
        __syncthreads();
        // Phase B: exclusive suffix of chunk totals
        if (tid == 0) {
            float run = 0.f;
            for (int c = nc - 1; c >= 0; c--) {
                float tc = ctot[c];
                ctot[c] = run;
                run += tc;
            }
        }
        __syncthreads();
        // Phase C: prod -> sp -> A, write new s
        {
            float ut = s_ut[bi], dt = s_dt[bi];
            for (int tau = tid; tau < n; tau += 256) {
                float so_ = sorig[tau];
                float prod = (ssuf[tau] + ctot[tau >> 5]) - so_;  // excl. suffix sum
                float sp = fmaxf(0.f, so_ - fmaxf(0.f, ut - prod));
                if (tau == t) sp = dt;
                float inner = fmaxf(0.f, 1.f - prod - sp);
                aA[tau] = fminf(sp, inner);
                g_s[b * MAXT + tau] = sp;
            }
        }
        __syncthreads();
        // Phase D: rt[d] = sum_tau A[tau] * V[b][tau][d]
        {
            int d = tid & 63;
            int grp = tid >> 6;
            float racc = 0.f;
            for (int tau = grp; tau < n; tau += 4)
                racc = fmaf(aA[tau], g_V[((size_t)b * MAXT + tau) * STK + d], racc);
            part[grp][d] = racc;
        }
        __syncthreads();
        if (tid < STK)
            g_rt[b * STK + tid] = part[0][tid] + part[1][tid] + part[2][tid] + part[3][tid];
        __syncthreads();
    }

    // Phase E: log-softmax of ot (out[:,64:192]) for output steps
    if (t >= OUT_T0) {
        const int bi = tid >> 7;      // 0..1
        const int q = tid & 127;      // 0..127 logits per batch
        float v = osh[bi][STK + q];
        float m = v;
#pragma unroll
        for (int d = 16; d; d >>= 1) m = fmaxf(m, __shfl_xor_sync(0xffffffffu, m, d));
        if (lane == 0) redm[warp] = m;
        __syncthreads();
        if (tid < 2)
            redv[tid] = fmaxf(fmaxf(redm[tid * 4 + 0], redm[tid * 4 + 1]),
                              fmaxf(redm[tid * 4 + 2], redm[tid * 4 + 3]));
        __syncthreads();
        float mm = redv[bi];
        float e = expf(v - mm);
        float s = e;
#pragma unroll
        for (int d = 16; d; d >>= 1) s += __shfl_xor_sync(0xffffffffu, s, d);
        if (lane == 0) redm[warp] = s;
        __syncthreads();
        if (tid < 2)
            redl[tid] = redv[tid] + logf(redm[tid * 4 + 0] + redm[tid * 4 + 1] +
                                         redm[tid * 4 + 2] + redm[tid * 4 + 3]);
        __syncthreads();
        int b = b0 + bi;
        out[((size_t)(t - OUT_T0) * BATCH + b) * IN_DIM + q] = v - redl[bi];
    }
}

// ---------------- launch ----------------
extern "C" void kernel_launch(void* const* d_in, const int* in_sizes, int n_in,
                              void* d_out, int out_size)
{
    (void)in_sizes; (void)n_in; (void)out_size;
    const float* x   = (const float*)d_in[0];
    const float* Wih = (const float*)d_in[1];
    const float* bih = (const float*)d_in[2];
    const float* Whh = (const float*)d_in[3];
    const float* bhh = (const float*)d_in[4];
    const float* Wr  = (const float*)d_in[5];
    const float* br  = (const float*)d_in[6];
    float* out = (float*)d_out;

    k_prep<<<512, 256>>>(Wih, bih, Whh, bhh, Wr);

    for (int t = 0; t < NSTEPS; t++) {
        k_gates<<<dim3(GD / BN, BATCH / BM), 256>>>(x, t);
        k_readout_stack<<<BATCH / 2, 256>>>(br, out, t);
    }
}

// round 11
// speedup vs baseline: 2.0350x; 1.0973x over previous
#include <cuda_runtime.h>
#include <math.h>
#include <stdint.h>

// ---------------- problem constants ----------------
#define BATCH   128
#define IN_DIM  128
#define HID     512
#define STK     64
#define GD      2048            // 4*HID gate rows
#define KIN     (IN_DIM + STK)  // 192
#define KTOT    (KIN + HID)     // 704 combined K
#define MAXT    259
#define NSTEPS  259
#define PH1_LAST 128            // t<=128 uses x[t]; t>=129 x==0
#define OUT_T0  129
#define RDIM    194             // STK + IN_DIM + 2

#define NKSTEP  88              // 704/8 global k-steps
#define N8TOT   256             // 2048/8 n8 tiles

// ---------------- persistent device state ----------------
// B (gates weights) pre-formatted into mma fragment layout, tf32 hi/lo:
// [n8(256)][kstep(88)][hilo(2)][lane(32)*2 + slot]  -> 11.5 MB, L2-resident
__device__ float g_Bf[N8TOT * NKSTEP * 2 * 64];
__device__ float g_bias[GD];            // bih+bhh, gate-interleaved (n = 4*j+gate)
__device__ float g_WrT[HID * RDIM];     // Wr transposed: [k][r]
__device__ float g_h[2][BATCH * HID];   // ping-pong hidden
__device__ float g_c[BATCH * HID];
__device__ float g_rt[BATCH * STK];
__device__ float g_s[BATCH * MAXT];
__device__ float g_V[BATCH * MAXT * STK];

__device__ __forceinline__ uint32_t f2tf(float v) {
    uint32_t r;
    asm("cvt.rna.tf32.f32 %0, %1;" : "=r"(r) : "f"(v));
    return r;
}

__device__ __forceinline__ void mma_tf32(float* c, const uint32_t* a, const uint32_t* b) {
    asm volatile(
        "mma.sync.aligned.m16n8k8.row.col.f32.tf32.tf32.f32 "
        "{%0,%1,%2,%3}, {%4,%5,%6,%7}, {%8,%9}, {%0,%1,%2,%3};\n"
        : "+f"(c[0]), "+f"(c[1]), "+f"(c[2]), "+f"(c[3])
        : "r"(a[0]), "r"(a[1]), "r"(a[2]), "r"(a[3]),
          "r"(b[0]), "r"(b[1]));
}

// ---------------- prep: format weights + zero state ----------------
__global__ void k_prep(const float* __restrict__ Wih, const float* __restrict__ bih,
                       const float* __restrict__ Whh, const float* __restrict__ bhh,
                       const float* __restrict__ Wr)
{
    int idx = blockIdx.x * blockDim.x + threadIdx.x;
    int nthreads = gridDim.x * blockDim.x;

    // gates weights -> gate-interleaved -> tf32 hi/lo fragment layout
    for (int i = idx; i < GD * KTOT; i += nthreads) {
        int n = i / KTOT, k = i - n * KTOT;
        int j = n >> 2, gate = n & 3;
        int src = gate * HID + j;
        float v = (k < KIN) ? Wih[src * KIN + k] : Whh[src * HID + (k - KIN)];
        uint32_t hi = f2tf(v);
        float lo = v - __uint_as_float(hi);
        int n8 = n >> 3, g = n & 7;
        int ks = k >> 3, kk = k & 7, tig = kk & 3, kh = kk >> 2;
        int lane = g * 4 + tig;
        int base = ((n8 * NKSTEP + ks) * 2) * 64 + lane * 2 + kh;
        g_Bf[base]      = __uint_as_float(hi);
        g_Bf[base + 64] = lo;
    }
    for (int n = idx; n < GD; n += nthreads) {
        int j = n >> 2, gate = n & 3;
        int src = gate * HID + j;
        g_bias[n] = bih[src] + bhh[src];
    }
    for (int i = idx; i < HID * RDIM; i += nthreads) {
        int k = i / RDIM, r = i - k * RDIM;
        g_WrT[i] = Wr[r * HID + k];
    }
    for (int i = idx; i < BATCH * HID; i += nthreads) { g_h[0][i] = 0.f; g_c[i] = 0.f; }
    for (int i = idx; i < BATCH * STK; i += nthreads) g_rt[i] = 0.f;
    for (int i = idx; i < BATCH * MAXT; i += nthreads) g_s[i] = 0.f;
}

// ---------------- K1: 3xTF32 tensor-core gates GEMM + fused LSTM cell ------
// gates(128 x 2048) = [x_t | rt | h_prev](128 x 704) @ Wg^T
// Tile: BM=64 (batch) x BN=32 (gates), grid (64,2)=128 blocks, 256 thr (8 warps).
// Warps: 4(M) x 2(N); each warp = m16 x n16 (2 n8 tiles).
// K chunks of 32 (4 ksteps), double-buffered smem; A staged fp32, split hi/lo
// at fragment load; B pre-formatted in global (pure coalesced copy).
__global__ void __launch_bounds__(256, 1)
k_gates(const float* __restrict__ x, int t)
{
    const int cur = t & 1;
    const float* __restrict__ hprev = g_h[cur];
    float* __restrict__ hnew = g_h[cur ^ 1];

    // sA: [buf][m16(4)][ks(4)][lane(32)][slot(4)] fp32  = 2*2048 floats (16KB)
    // sB: [buf][n8(4)][ks(4)][hilo(2)][64]               = 2*2048 floats (16KB)
    __shared__ __align__(16) float sA[2][2048];
    __shared__ __align__(16) float sB[2][2048];

    const int tid  = threadIdx.x;
    const int lane = tid & 31;
    const int warp = tid >> 5;
    const int mw = warp >> 1;    // 0..3  m16 row
    const int nw = warp & 1;     // 0..1  n16 col
    const int bn0 = blockIdx.x * 32;
    const int bm0 = blockIdx.y * 64;
    const int n8base = blockIdx.x * 4;
    const float* __restrict__ xrow = x + (size_t)t * BATCH * IN_DIM;

    const int cBeg = (t <= PH1_LAST) ? 0 : 4;  // phase 2: x chunks are zero
    const int nC = 22 - cBeg;

    // thread's 8 A staging elements: k = tid&31, b_e = warp + 8*e (fixed)
    const int kA = tid & 31;
    int aAddr[8];
#pragma unroll
    for (int e = 0; e < 8; e++) {
        int b = warp + 8 * e;
        int m16 = b >> 4, r = b & 15, g = r & 7, h8 = r >> 3;
        int ks = kA >> 3, kk = kA & 7, tig = kk & 3, kh = kk >> 2;
        aAddr[e] = ((m16 * 4 + ks) * 32 + (g * 4 + tig)) * 4 + (kh * 2 + h8);
    }
    // B staging: 2 float4 per thread
    const int n8l0 = (tid >> 7) & 1;         // j=0 -> 0/1
    const int n8l1 = n8l0 + 2;               // j=1 -> 2/3
    const int wB = tid & 127;
    const float4* __restrict__ Bf4 = reinterpret_cast<const float4*>(g_Bf);
    float4* sB4_0 = reinterpret_cast<float4*>(&sB[0][0]);
    float4* sB4_1 = reinterpret_cast<float4*>(&sB[1][0]);

    float acc[2][4];
#pragma unroll
    for (int i = 0; i < 2; i++)
#pragma unroll
        for (int j = 0; j < 4; j++) acc[i][j] = 0.f;

    // chunk -> A source (each 32-wide chunk lies in exactly one region)
    auto loadA = [&](int c, int e) -> float {
        int b = bm0 + warp + 8 * e;
        int k0 = c * 32 + kA;
        if (k0 < IN_DIM)   return xrow[b * IN_DIM + k0];
        if (k0 < KIN)      return g_rt[b * STK + (k0 - IN_DIM)];
        return hprev[b * HID + (k0 - KIN)];
    };

    // ---- prologue: chunk cBeg directly into buffer 0 ----
    {
        const int c = cBeg;
#pragma unroll
        for (int e = 0; e < 8; e++) sA[0][aAddr[e]] = loadA(c, e);
        sB4_0[n8l0 * 128 + wB] = Bf4[((n8base + n8l0) * NKSTEP + c * 4) * 32 + wB];
        sB4_0[n8l1 * 128 + wB] = Bf4[((n8base + n8l1) * NKSTEP + c * 4) * 32 + wB];
    }
    __syncthreads();

    for (int it = 0; it < nC; ++it) {
        const int p = it & 1;
        const bool more = (it + 1 < nC);
        float rA[8];
        float4 rB0, rB1;
        if (more) {
            const int c = cBeg + it + 1;
#pragma unroll
            for (int e = 0; e < 8; e++) rA[e] = loadA(c, e);
            rB0 = Bf4[((n8base + n8l0) * NKSTEP + c * 4) * 32 + wB];
            rB1 = Bf4[((n8base + n8l1) * NKSTEP + c * 4) * 32 + wB];
        }

#pragma unroll
        for (int ks = 0; ks < 4; ks++) {
            float4 af = *reinterpret_cast<const float4*>(
                &sA[p][((mw * 4 + ks) * 32 + lane) * 4]);
            uint32_t ahi[4], alo[4];
            ahi[0] = f2tf(af.x); alo[0] = __float_as_uint(af.x - __uint_as_float(ahi[0]));
            ahi[1] = f2tf(af.y); alo[1] = __float_as_uint(af.y - __uint_as_float(ahi[1]));
            ahi[2] = f2tf(af.z); alo[2] = __float_as_uint(af.z - __uint_as_float(ahi[2]));
            ahi[3] = f2tf(af.w); alo[3] = __float_as_uint(af.w - __uint_as_float(ahi[3]));
#pragma unroll
            for (int ni = 0; ni < 2; ni++) {
                const int n8l = nw * 2 + ni;
                const float* bb = &sB[p][((n8l * 4 + ks) * 2) * 64 + lane * 2];
                uint2 bhiu = *reinterpret_cast<const uint2*>(bb);
                uint2 blou = *reinterpret_cast<const uint2*>(bb + 64);
                uint32_t bh[2] = {bhiu.x, bhiu.y};
                uint32_t bl[2] = {blou.x, blou.y};
                mma_tf32(acc[ni], ahi, bh);
                mma_tf32(acc[ni], alo, bh);
                mma_tf32(acc[ni], ahi, bl);
            }
        }

        if (more) {
            const int q = p ^ 1;
#pragma unroll
            for (int e = 0; e < 8; e++) sA[q][aAddr[e]] = rA[e];
            float4* sBq = q ? sB4_1 : sB4_0;
            sBq[n8l0 * 128 + wB] = rB0;
            sBq[n8l1 * 128 + wB] = rB1;
        }
        __syncthreads();
    }

    // ---- epilogue: C fragments -> smem gates buffer -> fused LSTM cell ----
    float* g32 = &sA[0][0];   // reuse as [64][32]
    {
        const int r0 = mw * 16 + (lane >> 2);
        const int tig = lane & 3;
#pragma unroll
        for (int ni = 0; ni < 2; ni++) {
            int col = (nw * 2 + ni) * 8 + tig * 2;
            g32[r0 * 32 + col]           = acc[ni][0];
            g32[r0 * 32 + col + 1]       = acc[ni][1];
            g32[(r0 + 8) * 32 + col]     = acc[ni][2];
            g32[(r0 + 8) * 32 + col + 1] = acc[ni][3];
        }
    }
    __syncthreads();

#pragma unroll
    for (int i = 0; i < 2; i++) {
        int o = tid + i * 256;       // 0..511
        int b = o >> 3;              // 0..63 local batch
        int u = o & 7;               // local unit
        float4 gg = *reinterpret_cast<const float4*>(&g32[b * 32 + u * 4]);
        float4 bb = *reinterpret_cast<const float4*>(&g_bias[bn0 + u * 4]);
        float gi = gg.x + bb.x;
        float gf = gg.y + bb.y;
        float gc = gg.z + bb.z;
        float go = gg.w + bb.w;
        float si = 1.f / (1.f + expf(-gi));
        float sf = 1.f / (1.f + expf(-gf));
        float so = 1.f / (1.f + expf(-go));
        float tg = tanhf(gc);
        int bg = bm0 + b;
        int j = blockIdx.x * 8 + u;
        float cold = g_c[bg * HID + j];
        float cnew = sf * cold + si * tg;
        g_c[bg * HID + j] = cnew;
        hnew[bg * HID + j] = so * tanhf(cnew);
    }
}

// ---------------- K2: readout GEMM + stack update + (phase2) log-softmax ----
// 64 blocks x 256 threads; each block owns 2 batches.
__global__ void __launch_bounds__(256, 1)
k_readout_stack(const float* __restrict__ br, float* __restrict__ out, int t)
{
    const float* __restrict__ h = g_h[(t & 1) ^ 1];  // h_new from K1

    __shared__ float hsh[2][HID];
    __shared__ float osh[2][RDIM];
    __shared__ float s_ut[2], s_dt[2];
    __shared__ float ssuf[272];
    __shared__ float sorig[272];
    __shared__ float aA[272];
    __shared__ float ctot[16];
    __shared__ float part[4][STK];
    __shared__ float redm[8], redv[2], redl[2];

    const int tid = threadIdx.x;
    const int lane = tid & 31;
    const int warp = tid >> 5;
    const int b0 = blockIdx.x * 2;

#pragma unroll
    for (int i = 0; i < 4; i++) {
        int idx = tid + i * 256;
        hsh[idx >> 9][idx & 511] = h[(b0 + (idx >> 9)) * HID + (idx & 511)];
    }
    __syncthreads();

    if (tid < RDIM) {
        const int r = tid;
        float a0 = br[r], a1 = a0;
#pragma unroll 8
        for (int k = 0; k < HID; k++) {
            float w = g_WrT[k * RDIM + r];
            a0 = fmaf(hsh[0][k], w, a0);
            a1 = fmaf(hsh[1][k], w, a1);
        }
        osh[0][r] = a0; osh[1][r] = a1;
        if (r < STK) {
            g_V[((size_t)(b0 + 0) * MAXT + t) * STK + r] = a0;
            g_V[((size_t)(b0 + 1) * MAXT + t) * STK + r] = a1;
        }
    }
    __syncthreads();
    if (tid < 2) {
        s_ut[tid] = 1.f / (1.f + expf(-osh[tid][RDIM - 2]));
        s_dt[tid] = 1.f / (1.f + expf(-osh[tid][RDIM - 1]));
    }
    __syncthreads();

    const int n = t + 1;
    const int nc = (n + 31) >> 5;

    for (int bi = 0; bi < 2; bi++) {
        const int b = b0 + bi;
        for (int c = warp; c * 32 < n; c += 8) {
            int tau = c * 32 + lane;
            float v = (tau < n) ? g_s[b * MAXT + tau] : 0.f;
            if (tau < n) sorig[tau] = v;
#pragma unroll
            for (int d = 1; d < 32; d <<= 1) {
                float o = __shfl_down_sync(0xffffffffu, v, d);
                if (lane + d < 32) v += o;
            }
            if (tau < n) ssuf[tau] = v;
            if (lane == 0) ctot[c] = v;
        }
        __syncthreads();
        if (tid == 0) {
            float run = 0.f;
            for (int c = nc - 1; c >= 0; c--) {
                float tc = ctot[c];
                ctot[c] = run;
                run += tc;
            }
        }
        __syncthreads();
        {
            float ut = s_ut[bi], dt = s_dt[bi];
            for (int tau = tid; tau < n; tau += 256) {
                float so_ = sorig[tau];
                float prod = (ssuf[tau] + ctot[tau >> 5]) - so_;
                float sp = fmaxf(0.f, so_ - fmaxf(0.f, ut - prod));
                if (tau == t) sp = dt;
                float inner = fmaxf(0.f, 1.f - prod - sp);
                aA[tau] = fminf(sp, inner);
                g_s[b * MAXT + tau] = sp;
            }
        }
        __syncthreads();
        {
            int d = tid & 63;
            int grp = tid >> 6;
            float racc = 0.f;
            for (int tau = grp; tau < n; tau += 4)
                racc = fmaf(aA[tau], g_V[((size_t)b * MAXT + tau) * STK + d], racc);
            part[grp][d] = racc;
        }
        __syncthreads();
        if (tid < STK)
            g_rt[b * STK + tid] = part[0][tid] + part[1][tid] + part[2][tid] + part[3][tid];
        __syncthreads();
    }

    if (t >= OUT_T0) {
        const int bi = tid >> 7;
        const int q = tid & 127;
        float v = osh[bi][STK + q];
        float m = v;
#pragma unroll
        for (int d = 16; d; d >>= 1) m = fmaxf(m, __shfl_xor_sync(0xffffffffu, m, d));
        if (lane == 0) redm[warp] = m;
        __syncthreads();
        if (tid < 2)
            redv[tid] = fmaxf(fmaxf(redm[tid * 4 + 0], redm[tid * 4 + 1]),
                              fmaxf(redm[tid * 4 + 2], redm[tid * 4 + 3]));
        __syncthreads();
        float mm = redv[bi];
        float e = expf(v - mm);
        float s = e;
#pragma unroll
        for (int d = 16; d; d >>= 1) s += __shfl_xor_sync(0xffffffffu, s, d);
        if (lane == 0) redm[warp] = s;
        __syncthreads();
        if (tid < 2)
            redl[tid] = redv[tid] + logf(redm[tid * 4 + 0] + redm[tid * 4 + 1] +
                                         redm[tid * 4 + 2] + redm[tid * 4 + 3]);
        __syncthreads();
        int b = b0 + bi;
        out[((size_t)(t - OUT_T0) * BATCH + b) * IN_DIM + q] = v - redl[bi];
    }
}

// ---------------- launch ----------------
extern "C" void kernel_launch(void* const* d_in, const int* in_sizes, int n_in,
                              void* d_out, int out_size)
{
    (void)in_sizes; (void)n_in; (void)out_size;
    const float* x   = (const float*)d_in[0];
    const float* Wih = (const float*)d_in[1];
    const float* bih = (const float*)d_in[2];
    const float* Whh = (const float*)d_in[3];
    const float* bhh = (const float*)d_in[4];
    const float* Wr  = (const float*)d_in[5];
    const float* br  = (const float*)d_in[6];
    float* out = (float*)d_out;

    k_prep<<<512, 256>>>(Wih, bih, Whh, bhh, Wr);

    for (int t = 0; t < NSTEPS; t++) {
        k_gates<<<dim3(GD / 32, BATCH / 64), 256>>>(x, t);
        k_readout_stack<<<BATCH / 2, 256>>>(br, out, t);
    }
}

// round 12
// speedup vs baseline: 2.4300x; 1.1941x over previous
#include <cuda_runtime.h>
#include <math.h>
#include <stdint.h>

// ---------------- problem constants ----------------
#define BATCH   128
#define IN_DIM  128
#define HID     512
#define STK     64
#define GD      2048            // 4*HID gate rows
#define KIN     (IN_DIM + STK)  // 192
#define KTOT    (KIN + HID)     // 704 combined K
#define MAXT    259
#define NSTEPS  259
#define PH1_LAST 128            // t<=128 uses x[t]; t>=129 x==0
#define OUT_T0  129
#define RDIM    194             // STK + IN_DIM + 2

#define NKSTEP  88              // 704/8 global k-steps
#define N8TOT   256             // 2048/8 n8 tiles

// ---------------- persistent device state ----------------
// B (gates weights) pre-formatted into mma fragment layout, tf32 hi/lo:
// [n8(256)][kstep(88)][hilo(2)][lane(32)*2 + slot]  -> 11.5 MB, L2-resident
__device__ float g_Bf[N8TOT * NKSTEP * 2 * 64];
__device__ float g_bias[GD];            // bih+bhh, gate-interleaved (n = 4*j+gate)
__device__ float g_WrT[HID * RDIM];     // Wr transposed: [k][r]
__device__ float g_h[2][BATCH * HID];   // ping-pong hidden
__device__ float g_c[BATCH * HID];
__device__ float g_rt[BATCH * STK];
__device__ float g_s[BATCH * MAXT];
__device__ float g_V[BATCH * MAXT * STK];

__device__ __forceinline__ uint32_t f2tf(float v) {
    uint32_t r;
    asm("cvt.rna.tf32.f32 %0, %1;" : "=r"(r) : "f"(v));
    return r;
}

__device__ __forceinline__ void mma_tf32(float* c, const uint32_t* a, const uint32_t* b) {
    asm volatile(
        "mma.sync.aligned.m16n8k8.row.col.f32.tf32.tf32.f32 "
        "{%0,%1,%2,%3}, {%4,%5,%6,%7}, {%8,%9}, {%0,%1,%2,%3};\n"
        : "+f"(c[0]), "+f"(c[1]), "+f"(c[2]), "+f"(c[3])
        : "r"(a[0]), "r"(a[1]), "r"(a[2]), "r"(a[3]),
          "r"(b[0]), "r"(b[1]));
}

// ---------------- prep: format weights + zero state ----------------
__global__ void k_prep(const float* __restrict__ Wih, const float* __restrict__ bih,
                       const float* __restrict__ Whh, const float* __restrict__ bhh,
                       const float* __restrict__ Wr)
{
    int idx = blockIdx.x * blockDim.x + threadIdx.x;
    int nthreads = gridDim.x * blockDim.x;

    // gates weights -> gate-interleaved -> tf32 hi/lo fragment layout
    for (int i = idx; i < GD * KTOT; i += nthreads) {
        int n = i / KTOT, k = i - n * KTOT;
        int j = n >> 2, gate = n & 3;
        int src = gate * HID + j;
        float v = (k < KIN) ? Wih[src * KIN + k] : Whh[src * HID + (k - KIN)];
        uint32_t hi = f2tf(v);
        float lo = v - __uint_as_float(hi);
        int n8 = n >> 3, g = n & 7;
        int ks = k >> 3, kk = k & 7, tig = kk & 3, kh = kk >> 2;
        int lane = g * 4 + tig;
        int base = ((n8 * NKSTEP + ks) * 2) * 64 + lane * 2 + kh;
        g_Bf[base]      = __uint_as_float(hi);
        g_Bf[base + 64] = lo;
    }
    for (int n = idx; n < GD; n += nthreads) {
        int j = n >> 2, gate = n & 3;
        int src = gate * HID + j;
        g_bias[n] = bih[src] + bhh[src];
    }
    for (int i = idx; i < HID * RDIM; i += nthreads) {
        int k = i / RDIM, r = i - k * RDIM;
        g_WrT[i] = Wr[r * HID + k];
    }
    for (int i = idx; i < BATCH * HID; i += nthreads) { g_h[0][i] = 0.f; g_c[i] = 0.f; }
    for (int i = idx; i < BATCH * STK; i += nthreads) g_rt[i] = 0.f;
    for (int i = idx; i < BATCH * MAXT; i += nthreads) g_s[i] = 0.f;
}

// ---------------- K1: 3xTF32 tensor-core gates GEMM + fused LSTM cell ------
// gates(128 x 2048) = [x_t | rt | h_prev](128 x 704) @ Wg^T
// Tile: BM=32 (batch) x BN=32 (gates). Grid (64,4) = 256 blocks -> 2 blocks/SM.
// 8 warps: 2(M) x 4(N); each warp = m16 x n8 (one n8 tile), 12 MMAs/iter.
// K chunks of 32 (4 ksteps), double-buffered smem, register-staged loads.
__global__ void __launch_bounds__(256, 2)
k_gates(const float* __restrict__ x, int t)
{
    const int cur = t & 1;
    const float* __restrict__ hprev = g_h[cur];
    float* __restrict__ hnew = g_h[cur ^ 1];

    // sA: [buf][m16(2)][ks(4)][lane(32)][slot(4)] fp32 = 2*1024 floats (8KB)
    // sB: [buf][n8(4)][ks(4)][hilo(2)][64]              = 2*2048 floats (16KB)
    __shared__ __align__(16) float sA[2][1024];
    __shared__ __align__(16) float sB[2][2048];

    const int tid  = threadIdx.x;
    const int lane = tid & 31;
    const int warp = tid >> 5;
    const int mw  = warp >> 2;   // 0..1  m16 row
    const int nwl = warp & 3;    // 0..3  n8 tile
    const int bn0 = blockIdx.x * 32;
    const int bm0 = blockIdx.y * 32;
    const int n8base = blockIdx.x * 4;
    const float* __restrict__ xrow = x + (size_t)t * BATCH * IN_DIM;

    const int cBeg = (t <= PH1_LAST) ? 0 : 4;  // phase 2: x chunks are zero
    const int nC = 22 - cBeg;

    // thread's 4 A staging elements: k = tid&31, b_e = warp + 8*e
    const int kA = tid & 31;
    int aAddr[4];
#pragma unroll
    for (int e = 0; e < 4; e++) {
        int b = warp + 8 * e;            // 0..31
        int m16 = b >> 4, r = b & 15, g = r & 7, h8 = r >> 3;
        int ks = kA >> 3, kk = kA & 7, tig = kk & 3, kh = kk >> 2;
        aAddr[e] = ((m16 * 4 + ks) * 32 + (g * 4 + tig)) * 4 + (kh * 2 + h8);
    }
    // B staging: 2 float4 per thread
    const int n8l0 = (tid >> 7) & 1;     // 0/1
    const int n8l1 = n8l0 + 2;           // 2/3
    const int wB = tid & 127;
    const float4* __restrict__ Bf4 = reinterpret_cast<const float4*>(g_Bf);
    float4* sB4_0 = reinterpret_cast<float4*>(&sB[0][0]);
    float4* sB4_1 = reinterpret_cast<float4*>(&sB[1][0]);

    float acc[4] = {0.f, 0.f, 0.f, 0.f};

    // chunk -> A source (each 32-wide chunk lies in exactly one region)
    auto loadA = [&](int c, int e) -> float {
        int b = bm0 + warp + 8 * e;
        int k0 = c * 32 + kA;
        if (k0 < IN_DIM)   return xrow[b * IN_DIM + k0];
        if (k0 < KIN)      return g_rt[b * STK + (k0 - IN_DIM)];
        return hprev[b * HID + (k0 - KIN)];
    };

    // ---- prologue: chunk cBeg directly into buffer 0 ----
    {
        const int c = cBeg;
#pragma unroll
        for (int e = 0; e < 4; e++) sA[0][aAddr[e]] = loadA(c, e);
        sB4_0[n8l0 * 128 + wB] = Bf4[((n8base + n8l0) * NKSTEP + c * 4) * 32 + wB];
        sB4_0[n8l1 * 128 + wB] = Bf4[((n8base + n8l1) * NKSTEP + c * 4) * 32 + wB];
    }
    __syncthreads();

    for (int it = 0; it < nC; ++it) {
        const int p = it & 1;
        const bool more = (it + 1 < nC);
        float rA[4];
        float4 rB0, rB1;
        if (more) {
            const int c = cBeg + it + 1;
#pragma unroll
            for (int e = 0; e < 4; e++) rA[e] = loadA(c, e);
            rB0 = Bf4[((n8base + n8l0) * NKSTEP + c * 4) * 32 + wB];
            rB1 = Bf4[((n8base + n8l1) * NKSTEP + c * 4) * 32 + wB];
        }

#pragma unroll
        for (int ks = 0; ks < 4; ks++) {
            float4 af = *reinterpret_cast<const float4*>(
                &sA[p][((mw * 4 + ks) * 32 + lane) * 4]);
            uint32_t ahi[4], alo[4];
            ahi[0] = f2tf(af.x); alo[0] = __float_as_uint(af.x - __uint_as_float(ahi[0]));
            ahi[1] = f2tf(af.y); alo[1] = __float_as_uint(af.y - __uint_as_float(ahi[1]));
            ahi[2] = f2tf(af.z); alo[2] = __float_as_uint(af.z - __uint_as_float(ahi[2]));
            ahi[3] = f2tf(af.w); alo[3] = __float_as_uint(af.w - __uint_as_float(ahi[3]));
            const float* bb = &sB[p][((nwl * 4 + ks) * 2) * 64 + lane * 2];
            uint2 bhiu = *reinterpret_cast<const uint2*>(bb);
            uint2 blou = *reinterpret_cast<const uint2*>(bb + 64);
            uint32_t bh[2] = {bhiu.x, bhiu.y};
            uint32_t bl[2] = {blou.x, blou.y};
            mma_tf32(acc, ahi, bh);
            mma_tf32(acc, alo, bh);
            mma_tf32(acc, ahi, bl);
        }

        if (more) {
            const int q = p ^ 1;
#pragma unroll
            for (int e = 0; e < 4; e++) sA[q][aAddr[e]] = rA[e];
            float4* sBq = q ? sB4_1 : sB4_0;
            sBq[n8l0 * 128 + wB] = rB0;
            sBq[n8l1 * 128 + wB] = rB1;
        }
        __syncthreads();
    }

    // ---- epilogue: C fragments -> smem gates buffer -> fused LSTM cell ----
    float* g32 = &sA[0][0];   // reuse as [32][32]
    {
        const int r0 = mw * 16 + (lane >> 2);
        const int col = nwl * 8 + (lane & 3) * 2;
        g32[r0 * 32 + col]           = acc[0];
        g32[r0 * 32 + col + 1]       = acc[1];
        g32[(r0 + 8) * 32 + col]     = acc[2];
        g32[(r0 + 8) * 32 + col + 1] = acc[3];
    }
    __syncthreads();

    {
        int b = tid >> 3;            // 0..31 local batch
        int u = tid & 7;             // local unit
        float4 gg = *reinterpret_cast<const float4*>(&g32[b * 32 + u * 4]);
        float4 bb = *reinterpret_cast<const float4*>(&g_bias[bn0 + u * 4]);
        float gi = gg.x + bb.x;
        float gf = gg.y + bb.y;
        float gc = gg.z + bb.z;
        float go = gg.w + bb.w;
        float si = 1.f / (1.f + expf(-gi));
        float sf = 1.f / (1.f + expf(-gf));
        float so = 1.f / (1.f + expf(-go));
        float tg = tanhf(gc);
        int bg = bm0 + b;
        int j = blockIdx.x * 8 + u;
        float cold = g_c[bg * HID + j];
        float cnew = sf * cold + si * tg;
        g_c[bg * HID + j] = cnew;
        hnew[bg * HID + j] = so * tanhf(cnew);
    }
}

// ---------------- K2: readout GEMM + stack update + (phase2) log-softmax ----
// 64 blocks x 256 threads; each block owns 2 batches.
__global__ void __launch_bounds__(256, 1)
k_readout_stack(const float* __restrict__ br, float* __restrict__ out, int t)
{
    const float* __restrict__ h = g_h[(t & 1) ^ 1];  // h_new from K1

    __shared__ float hsh[2][HID];
    __shared__ float osh[2][RDIM];
    __shared__ float s_ut[2], s_dt[2];
    __shared__ float ssuf[272];
    __shared__ float sorig[272];
    __shared__ float aA[272];
    __shared__ float ctot[16];
    __shared__ float part[4][STK];
    __shared__ float redm[8], redv[2], redl[2];

    const int tid = threadIdx.x;
    const int lane = tid & 31;
    const int warp = tid >> 5;
    const int b0 = blockIdx.x * 2;

#pragma unroll
    for (int i = 0; i < 4; i++) {
        int idx = tid + i * 256;
        hsh[idx >> 9][idx & 511] = h[(b0 + (idx >> 9)) * HID + (idx & 511)];
    }
    __syncthreads();

    // readout with 4 independent k-chunk accumulator chains per batch
    if (tid < RDIM) {
        const int r = tid;
        float c00 = br[r], c01 = 0.f, c02 = 0.f, c03 = 0.f;
        float c10 = c00,   c11 = 0.f, c12 = 0.f, c13 = 0.f;
#pragma unroll 4
        for (int k = 0; k < 128; k++) {
            float w0 = g_WrT[(k      ) * RDIM + r];
            float w1 = g_WrT[(k + 128) * RDIM + r];
            float w2 = g_WrT[(k + 256) * RDIM + r];
            float w3 = g_WrT[(k + 384) * RDIM + r];
            c00 = fmaf(hsh[0][k      ], w0, c00);
            c01 = fmaf(hsh[0][k + 128], w1, c01);
            c02 = fmaf(hsh[0][k + 256], w2, c02);
            c03 = fmaf(hsh[0][k + 384], w3, c03);
            c10 = fmaf(hsh[1][k      ], w0, c10);
            c11 = fmaf(hsh[1][k + 128], w1, c11);
            c12 = fmaf(hsh[1][k + 256], w2, c12);
            c13 = fmaf(hsh[1][k + 384], w3, c13);
        }
        float a0 = (c00 + c01) + (c02 + c03);
        float a1 = (c10 + c11) + (c12 + c13);
        osh[0][r] = a0; osh[1][r] = a1;
        if (r < STK) {
            g_V[((size_t)(b0 + 0) * MAXT + t) * STK + r] = a0;
            g_V[((size_t)(b0 + 1) * MAXT + t) * STK + r] = a1;
        }
    }
    __syncthreads();
    if (tid < 2) {
        s_ut[tid] = 1.f / (1.f + expf(-osh[tid][RDIM - 2]));
        s_dt[tid] = 1.f / (1.f + expf(-osh[tid][RDIM - 1]));
    }
    __syncthreads();

    const int n = t + 1;
    const int nc = (n + 31) >> 5;

    for (int bi = 0; bi < 2; bi++) {
        const int b = b0 + bi;
        for (int c = warp; c * 32 < n; c += 8) {
            int tau = c * 32 + lane;
            float v = (tau < n) ? g_s[b * MAXT + tau] : 0.f;
            if (tau < n) sorig[tau] = v;
#pragma unroll
            for (int d = 1; d < 32; d <<= 1) {
                float o = __shfl_down_sync(0xffffffffu, v, d);
                if (lane + d < 32) v += o;
            }
            if (tau < n) ssuf[tau] = v;
            if (lane == 0) ctot[c] = v;
        }
        __syncthreads();
        if (tid == 0) {
            float run = 0.f;
            for (int c = nc - 1; c >= 0; c--) {
                float tc = ctot[c];
                ctot[c] = run;
                run += tc;
            }
        }
        __syncthreads();
        {
            float ut = s_ut[bi], dt = s_dt[bi];
            for (int tau = tid; tau < n; tau += 256) {
                float so_ = sorig[tau];
                float prod = (ssuf[tau] + ctot[tau >> 5]) - so_;
                float sp = fmaxf(0.f, so_ - fmaxf(0.f, ut - prod));
                if (tau == t) sp = dt;
                float inner = fmaxf(0.f, 1.f - prod - sp);
                aA[tau] = fminf(sp, inner);
                g_s[b * MAXT + tau] = sp;
            }
        }
        __syncthreads();
        {
            int d = tid & 63;
            int grp = tid >> 6;
            float racc = 0.f;
            for (int tau = grp; tau < n; tau += 4)
                racc = fmaf(aA[tau], g_V[((size_t)b * MAXT + tau) * STK + d], racc);
            part[grp][d] = racc;
        }
        __syncthreads();
        if (tid < STK)
            g_rt[b * STK + tid] = part[0][tid] + part[1][tid] + part[2][tid] + part[3][tid];
        __syncthreads();
    }

    if (t >= OUT_T0) {
        const int bi = tid >> 7;
        const int q = tid & 127;
        float v = osh[bi][STK + q];
        float m = v;
#pragma unroll
        for (int d = 16; d; d >>= 1) m = fmaxf(m, __shfl_xor_sync(0xffffffffu, m, d));
        if (lane == 0) redm[warp] = m;
        __syncthreads();
        if (tid < 2)
            redv[tid] = fmaxf(fmaxf(redm[tid * 4 + 0], redm[tid * 4 + 1]),
                              fmaxf(redm[tid * 4 + 2], redm[tid * 4 + 3]));
        __syncthreads();
        float mm = redv[bi];
        float e = expf(v - mm);
        float s = e;
#pragma unroll
        for (int d = 16; d; d >>= 1) s += __shfl_xor_sync(0xffffffffu, s, d);
        if (lane == 0) redm[warp] = s;
        __syncthreads();
        if (tid < 2)
            redl[tid] = redv[tid] + logf(redm[tid * 4 + 0] + redm[tid * 4 + 1] +
                                         redm[tid * 4 + 2] + redm[tid * 4 + 3]);
        __syncthreads();
        int b = b0 + bi;
        out[((size_t)(t - OUT_T0) * BATCH + b) * IN_DIM + q] = v - redl[bi];
    }
}

// ---------------- launch ----------------
extern "C" void kernel_launch(void* const* d_in, const int* in_sizes, int n_in,
                              void* d_out, int out_size)
{
    (void)in_sizes; (void)n_in; (void)out_size;
    const float* x   = (const float*)d_in[0];
    const float* Wih = (const float*)d_in[1];
    const float* bih = (const float*)d_in[2];
    const float* Whh = (const float*)d_in[3];
    const float* bhh = (const float*)d_in[4];
    const float* Wr  = (const float*)d_in[5];
    const float* br  = (const float*)d_in[6];
    float* out = (float*)d_out;

    k_prep<<<512, 256>>>(Wih, bih, Whh, bhh, Wr);

    for (int t = 0; t < NSTEPS; t++) {
        k_gates<<<dim3(GD / 32, BATCH / 32), 256>>>(x, t);
        k_readout_stack<<<BATCH / 2, 256>>>(br, out, t);
    }
}

// round 14
// speedup vs baseline: 2.4449x; 1.0061x over previous
#include <cuda_runtime.h>
#include <math.h>
#include <stdint.h>

// ---------------- problem constants ----------------
#define BATCH   128
#define IN_DIM  128
#define HID     512
#define STK     64
#define GD      2048            // 4*HID gate rows
#define KIN     (IN_DIM + STK)  // 192
#define KTOT    (KIN + HID)     // 704 combined K
#define MAXT    259
#define NSTEPS  259
#define PH1_LAST 128            // t<=128 uses x[t]; t>=129 x==0
#define OUT_T0  129
#define RDIM    194             // STK + IN_DIM + 2

#define NKSTEP  88              // 704/8 global k-steps
#define N8TOT   256             // 2048/8 n8 tiles

// ---------------- persistent device state ----------------
// B (gates weights) in mma fragment layout, tf32 hi/lo (11.5 MB, L2-resident)
__device__ float  g_Bf[N8TOT * NKSTEP * 2 * 64];
__device__ float  g_bias[GD];             // bih+bhh, gate-interleaved (n = 4*j+gate)
__device__ float  g_WrT[HID * RDIM];      // Wr transposed: [k][r]
__device__ float  g_h[2][BATCH * HID];    // plain h (read by K2)
__device__ float2 g_hHL[2][BATCH * HID];  // h pre-split (hi,lo) for MMA A
__device__ float2 g_rtHL[BATCH * STK];    // rt pre-split
__device__ float2 g_xHL[(PH1_LAST + 1) * BATCH * IN_DIM];  // x pre-split (phase 1)
__device__ float  g_c[BATCH * HID];
__device__ float  g_s[BATCH * MAXT];
__device__ float  g_V[BATCH * MAXT * STK];

__device__ __forceinline__ uint32_t f2tf(float v) {
    uint32_t r;
    asm("cvt.rna.tf32.f32 %0, %1;" : "=r"(r) : "f"(v));
    return r;
}

__device__ __forceinline__ float2 splitHL(float v) {
    uint32_t hi = f2tf(v);
    return make_float2(__uint_as_float(hi), v - __uint_as_float(hi));
}

__device__ __forceinline__ void mma_tf32(float* c, const uint32_t* a, const uint32_t* b) {
    asm volatile(
        "mma.sync.aligned.m16n8k8.row.col.f32.tf32.tf32.f32 "
        "{%0,%1,%2,%3}, {%4,%5,%6,%7}, {%8,%9}, {%0,%1,%2,%3};\n"
        : "+f"(c[0]), "+f"(c[1]), "+f"(c[2]), "+f"(c[3])
        : "r"(a[0]), "r"(a[1]), "r"(a[2]), "r"(a[3]),
          "r"(b[0]), "r"(b[1]));
}

__device__ __forceinline__ void cp16(void* smem_dst, const void* gmem_src) {
    unsigned d = (unsigned)__cvta_generic_to_shared(smem_dst);
    asm volatile("cp.async.cg.shared.global [%0], [%1], 16;" :: "r"(d), "l"(gmem_src));
}

// ---------------- prep: format weights, pre-split x, zero state ----------------
__global__ void k_prep(const float* __restrict__ x,
                       const float* __restrict__ Wih, const float* __restrict__ bih,
                       const float* __restrict__ Whh, const float* __restrict__ bhh,
                       const float* __restrict__ Wr)
{
    int idx = blockIdx.x * blockDim.x + threadIdx.x;
    int nthreads = gridDim.x * blockDim.x;

    // gates weights -> gate-interleaved -> tf32 hi/lo fragment layout
    for (int i = idx; i < GD * KTOT; i += nthreads) {
        int n = i / KTOT, k = i - n * KTOT;
        int j = n >> 2, gate = n & 3;
        int src = gate * HID + j;
        float v = (k < KIN) ? Wih[src * KIN + k] : Whh[src * HID + (k - KIN)];
        uint32_t hi = f2tf(v);
        float lo = v - __uint_as_float(hi);
        int n8 = n >> 3, g = n & 7;
        int ks = k >> 3, kk = k & 7, tig = kk & 3, kh = kk >> 2;
        int lane = g * 4 + tig;
        int base = ((n8 * NKSTEP + ks) * 2) * 64 + lane * 2 + kh;
        g_Bf[base]      = __uint_as_float(hi);
        g_Bf[base + 64] = lo;
    }
    for (int n = idx; n < GD; n += nthreads) {
        int j = n >> 2, gate = n & 3;
        int src = gate * HID + j;
        g_bias[n] = bih[src] + bhh[src];
    }
    for (int i = idx; i < HID * RDIM; i += nthreads) {
        int k = i / RDIM, r = i - k * RDIM;
        g_WrT[i] = Wr[r * HID + k];
    }
    // pre-split x (phase-1 steps only)
    const int XN = (PH1_LAST + 1) * BATCH * IN_DIM;
    for (int i = idx; i < XN; i += nthreads) g_xHL[i] = splitHL(x[i]);
    // zero recurrent state
    for (int i = idx; i < BATCH * HID; i += nthreads) {
        g_hHL[0][i] = make_float2(0.f, 0.f);
        g_h[0][i] = 0.f;
        g_c[i] = 0.f;
    }
    for (int i = idx; i < BATCH * STK; i += nthreads) g_rtHL[i] = make_float2(0.f, 0.f);
    for (int i = idx; i < BATCH * MAXT; i += nthreads) g_s[i] = 0.f;
}

// ---------------- K1: 3xTF32 tensor-core gates GEMM + fused LSTM cell ------
// gates(128 x 2048) = [x_t | rt | h_prev](128 x 704) @ Wg^T
// BM=32 x BN=32, grid (64,4)=256 blocks, 256 thr (8 warps: 2M x 4N, warp m16n8).
// A pre-split float2 staged row-linear via cp.async (stride 36 float2/row);
// B pre-split fragment layout staged via cp.async. Double-buffered.
#define A_STRIDE 36   // float2 per A row (32 data + 4 pad)

__global__ void __launch_bounds__(256, 2)
k_gates(int t)
{
    const int cur = t & 1;
    const float2* __restrict__ hHL = g_hHL[cur];
    float*  __restrict__ hnew   = g_h[cur ^ 1];
    float2* __restrict__ hnewHL = g_hHL[cur ^ 1];

    __shared__ __align__(16) float2 sA[2][32 * A_STRIDE];  // 2 x 9216B
    __shared__ __align__(16) float  sB[2][2048];           // 2 x 8192B

    const int tid  = threadIdx.x;
    const int lane = tid & 31;
    const int warp = tid >> 5;
    const int mw  = warp >> 2;   // 0..1  m16 row
    const int nwl = warp & 3;    // 0..3  n8 tile
    const int bn0 = blockIdx.x * 32;
    const int bm0 = blockIdx.y * 32;
    const int n8base = blockIdx.x * 4;

    const int cBeg = (t <= PH1_LAST) ? 0 : 4;  // phase 2: x chunks are zero
    const int nC = 22 - cBeg;

    // staging geometry (fixed per thread)
    const int aRow0 = tid >> 4;          // e=0 row (0..15)
    const int aSeg  = (tid & 15) * 2;    // float2 offset within row (16B granule)
    const int bTile0 = tid >> 7;         // e=0 tile (0..1)
    const int bSeg   = tid & 127;        // float4 index within tile

    // stage one K-chunk into buffer s  (per-buffer tile stride = 512 floats!)
    auto stage = [&](int s, int c) {
        const int k0 = c * 32;
#pragma unroll
        for (int e = 0; e < 2; e++) {
            int row = aRow0 + e * 16;
            int b = bm0 + row;
            const float2* src;
            if (k0 < IN_DIM)      src = g_xHL + ((size_t)t * BATCH + b) * IN_DIM + k0;
            else if (k0 < KIN)    src = g_rtHL + b * STK + (k0 - IN_DIM);
            else                  src = hHL + b * HID + (k0 - KIN);
            cp16(&sA[s][row * A_STRIDE + aSeg], src + aSeg);
        }
#pragma unroll
        for (int e = 0; e < 2; e++) {
            int tile = bTile0 + e * 2;
            const float4* src = reinterpret_cast<const float4*>(g_Bf)
                                + ((size_t)(n8base + tile) * NKSTEP + c * 4) * 32 + bSeg;
            cp16(&sB[s][tile * 512 + bSeg * 4], src);
        }
        asm volatile("cp.async.commit_group;");
    };

    float acc[4] = {0.f, 0.f, 0.f, 0.f};

    const int rbase = mw * 16 + (lane >> 2);
    const int kcol  = lane & 3;

    stage(0, cBeg);

    for (int it = 0; it < nC; ++it) {
        const int s = it & 1;
        const bool more = (it + 1 < nC);
        if (more) {
            stage(s ^ 1, cBeg + it + 1);
            asm volatile("cp.async.wait_group 1;");
        } else {
            asm volatile("cp.async.wait_group 0;");
        }
        __syncthreads();

#pragma unroll
        for (int ks = 0; ks < 4; ks++) {
            const float2* A0 = &sA[s][rbase * A_STRIDE + ks * 8 + kcol];
            float2 a00 = A0[0];
            float2 a10 = A0[8 * A_STRIDE];
            float2 a01 = A0[4];
            float2 a11 = A0[8 * A_STRIDE + 4];
            uint32_t ahi[4] = {__float_as_uint(a00.x), __float_as_uint(a10.x),
                               __float_as_uint(a01.x), __float_as_uint(a11.x)};
            uint32_t alo[4] = {__float_as_uint(a00.y), __float_as_uint(a10.y),
                               __float_as_uint(a01.y), __float_as_uint(a11.y)};
            const float* bb = &sB[s][((nwl * 4 + ks) * 2) * 64 + lane * 2];
            uint2 bhiu = *reinterpret_cast<const uint2*>(bb);
            uint2 blou = *reinterpret_cast<const uint2*>(bb + 64);
            uint32_t bh[2] = {bhiu.x, bhiu.y};
            uint32_t bl[2] = {blou.x, blou.y};
            mma_tf32(acc, ahi, bh);
            mma_tf32(acc, alo, bh);
            mma_tf32(acc, ahi, bl);
        }
        __syncthreads();
    }

    // ---- epilogue: C fragments -> smem -> fused LSTM cell ----
    float* g32 = reinterpret_cast<float*>(&sA[0][0]);   // reuse as [32][32]
    {
        const int r0 = mw * 16 + (lane >> 2);
        const int col = nwl * 8 + (lane & 3) * 2;
        g32[r0 * 32 + col]           = acc[0];
        g32[r0 * 32 + col + 1]       = acc[1];
        g32[(r0 + 8) * 32 + col]     = acc[2];
        g32[(r0 + 8) * 32 + col + 1] = acc[3];
    }
    __syncthreads();

    {
        int b = tid >> 3;            // 0..31 local batch
        int u = tid & 7;             // local unit
        float4 gg = *reinterpret_cast<const float4*>(&g32[b * 32 + u * 4]);
        float4 bb = *reinterpret_cast<const float4*>(&g_bias[bn0 + u * 4]);
        float gi = gg.x + bb.x;
        float gf = gg.y + bb.y;
        float gc = gg.z + bb.z;
        float go = gg.w + bb.w;
        float si = 1.f / (1.f + expf(-gi));
        float sf = 1.f / (1.f + expf(-gf));
        float so = 1.f / (1.f + expf(-go));
        float tg = tanhf(gc);
        int bg = bm0 + b;
        int j = blockIdx.x * 8 + u;
        float cold = g_c[bg * HID + j];
        float cnew = sf * cold + si * tg;
        g_c[bg * HID + j] = cnew;
        float hv = so * tanhf(cnew);
        hnew[bg * HID + j] = hv;
        hnewHL[bg * HID + j] = splitHL(hv);
    }
}

// ---------------- K2: readout GEMM + stack update + (phase2) log-softmax ----
// 64 blocks x 256 threads; each block owns 2 batches.
__global__ void __launch_bounds__(256, 1)
k_readout_stack(const float* __restrict__ br, float* __restrict__ out, int t)
{
    const float* __restrict__ h = g_h[(t & 1) ^ 1];  // h_new from K1

    __shared__ float hsh[2][HID];
    __shared__ float osh[2][RDIM];
    __shared__ float s_ut[2], s_dt[2];
    __shared__ float ssuf[272];
    __shared__ float sorig[272];
    __shared__ float aA[272];
    __shared__ float ctot[16];
    __shared__ float part[4][STK];
    __shared__ float redm[8], redv[2], redl[2];

    const int tid = threadIdx.x;
    const int lane = tid & 31;
    const int warp = tid >> 5;
    const int b0 = blockIdx.x * 2;

#pragma unroll
    for (int i = 0; i < 4; i++) {
        int idx = tid + i * 256;
        hsh[idx >> 9][idx & 511] = h[(b0 + (idx >> 9)) * HID + (idx & 511)];
    }
    __syncthreads();

    // readout with 4 independent k-chunk accumulator chains per batch
    if (tid < RDIM) {
        const int r = tid;
        float c00 = br[r], c01 = 0.f, c02 = 0.f, c03 = 0.f;
        float c10 = c00,   c11 = 0.f, c12 = 0.f, c13 = 0.f;
#pragma unroll 4
        for (int k = 0; k < 128; k++) {
            float w0 = g_WrT[(k      ) * RDIM + r];
            float w1 = g_WrT[(k + 128) * RDIM + r];
            float w2 = g_WrT[(k + 256) * RDIM + r];
            float w3 = g_WrT[(k + 384) * RDIM + r];
            c00 = fmaf(hsh[0][k      ], w0, c00);
            c01 = fmaf(hsh[0][k + 128], w1, c01);
            c02 = fmaf(hsh[0][k + 256], w2, c02);
            c03 = fmaf(hsh[0][k + 384], w3, c03);
            c10 = fmaf(hsh[1][k      ], w0, c10);
            c11 = fmaf(hsh[1][k + 128], w1, c11);
            c12 = fmaf(hsh[1][k + 256], w2, c12);
            c13 = fmaf(hsh[1][k + 384], w3, c13);
        }
        float a0 = (c00 + c01) + (c02 + c03);
        float a1 = (c10 + c11) + (c12 + c13);
        osh[0][r] = a0; osh[1][r] = a1;
        if (r < STK) {
            g_V[((size_t)(b0 + 0) * MAXT + t) * STK + r] = a0;
            g_V[((size_t)(b0 + 1) * MAXT + t) * STK + r] = a1;
        }
    }
    __syncthreads();
    if (tid < 2) {
        s_ut[tid] = 1.f / (1.f + expf(-osh[tid][RDIM - 2]));
        s_dt[tid] = 1.f / (1.f + expf(-osh[tid][RDIM - 1]));
    }
    __syncthreads();

    const int n = t + 1;
    const int nc = (n + 31) >> 5;

    for (int bi = 0; bi < 2; bi++) {
        const int b = b0 + bi;
        for (int c = warp; c * 32 < n; c += 8) {
            int tau = c * 32 + lane;
            float v = (tau < n) ? g_s[b * MAXT + tau] : 0.f;
            if (tau < n) sorig[tau] = v;
#pragma unroll
            for (int d = 1; d < 32; d <<= 1) {
                float o = __shfl_down_sync(0xffffffffu, v, d);
                if (lane + d < 32) v += o;
            }
            if (tau < n) ssuf[tau] = v;
            if (lane == 0) ctot[c] = v;
        }
        __syncthreads();
        if (tid == 0) {
            float run = 0.f;
            for (int c = nc - 1; c >= 0; c--) {
                float tc = ctot[c];
                ctot[c] = run;
                run += tc;
            }
        }
        __syncthreads();
        {
            float ut = s_ut[bi], dt = s_dt[bi];
            for (int tau = tid; tau < n; tau += 256) {
                float so_ = sorig[tau];
                float prod = (ssuf[tau] + ctot[tau >> 5]) - so_;
                float sp = fmaxf(0.f, so_ - fmaxf(0.f, ut - prod));
                if (tau == t) sp = dt;
                float inner = fmaxf(0.f, 1.f - prod - sp);
                aA[tau] = fminf(sp, inner);
                g_s[b * MAXT + tau] = sp;
            }
        }
        __syncthreads();
        {
            int d = tid & 63;
            int grp = tid >> 6;
            float racc = 0.f;
            for (int tau = grp; tau < n; tau += 4)
                racc = fmaf(aA[tau], g_V[((size_t)b * MAXT + tau) * STK + d], racc);
            part[grp][d] = racc;
        }
        __syncthreads();
        if (tid < STK) {
            float rv = part[0][tid] + part[1][tid] + part[2][tid] + part[3][tid];
            g_rtHL[b * STK + tid] = splitHL(rv);
        }
        __syncthreads();
    }

    if (t >= OUT_T0) {
        const int bi = tid >> 7;
        const int q = tid & 127;
        float v = osh[bi][STK + q];
        float m = v;
#pragma unroll
        for (int d = 16; d; d >>= 1) m = fmaxf(m, __shfl_xor_sync(0xffffffffu, m, d));
        if (lane == 0) redm[warp] = m;
        __syncthreads();
        if (tid < 2)
            redv[tid] = fmaxf(fmaxf(redm[tid * 4 + 0], redm[tid * 4 + 1]),
                              fmaxf(redm[tid * 4 + 2], redm[tid * 4 + 3]));
        __syncthreads();
        float mm = redv[bi];
        float e = expf(v - mm);
        float s = e;
#pragma unroll
        for (int d = 16; d; d >>= 1) s += __shfl_xor_sync(0xffffffffu, s, d);
        if (lane == 0) redm[warp] = s;
        __syncthreads();
        if (tid < 2)
            redl[tid] = redv[tid] + logf(redm[tid * 4 + 0] + redm[tid * 4 + 1] +
                                         redm[tid * 4 + 2] + redm[tid * 4 + 3]);
        __syncthreads();
        int b = b0 + bi;
        out[((size_t)(t - OUT_T0) * BATCH + b) * IN_DIM + q] = v - redl[bi];
    }
}

// ---------------- launch ----------------
extern "C" void kernel_launch(void* const* d_in, const int* in_sizes, int n_in,
                              void* d_out, int out_size)
{
    (void)in_sizes; (void)n_in; (void)out_size;
    const float* x   = (const float*)d_in[0];
    const float* Wih = (const float*)d_in[1];
    const float* bih = (const float*)d_in[2];
    const float* Whh = (const float*)d_in[3];
    const float* bhh = (const float*)d_in[4];
    const float* Wr  = (const float*)d_in[5];
    const float* br  = (const float*)d_in[6];
    float* out = (float*)d_out;

    k_prep<<<512, 256>>>(x, Wih, bih, Whh, bhh, Wr);

    for (int t = 0; t < NSTEPS; t++) {
        k_gates<<<dim3(GD / 32, BATCH / 32), 256>>>(t);
        k_readout_stack<<<BATCH / 2, 256>>>(br, out, t);
    }
}